// round 13
// baseline (speedup 1.0000x reference)
#include <cuda_runtime.h>
#include <cuda_fp16.h>
#include <math.h>

#define BATCH 4096
#define FEAT  40960
#define HID   1024
#define HID2  2048
#define NL1   64
#define NL2   32
#define GRP   32
#define NGRP  (BATCH / GRP)     // 128
#define NQ    4                 // k-quarters
#define QK    (HID2 / NQ)       // 512

// ---------------- static device scratch (no allocs allowed) ----------------
__device__ __half g_ftT[(size_t)FEAT * HID];             // 83.9 MB
__device__ __half g_h1[(size_t)BATCH * HID2];            // 16.8 MB
__device__ float  g_part[(size_t)NQ * NGRP * GRP * NL1]; // 4.2 MB l1 partials
__device__ int    g_done;        // transpose completion (self-resetting)
__device__ int    g_scan_done;   // scanner completion (self-resetting)

// =========================================================================
// Mega-kernel (round-4 logic + self-resetting counters):
//   CTAs [0, NT)        : transpose ft_w -> g_ftT (fp16), signal.
//   CTAs [NT, NT+BATCH) : scan -> wait -> gather -> h1 (fp16).
// The LAST scanner CTA resets both counters to 0 (all waits already passed),
// so no separate reset launch is needed and graph replays stay correct.
// =========================================================================
#define T1      256
#define NT      512
#define MAXIDX  256
#define NTILE_F (FEAT / 32)                 // 1280
#define NTILES  (NTILE_F * (HID / 64))      // 20480

__global__ __launch_bounds__(T1) void mega_kernel(
    const float* __restrict__ wf,    // [B, FEAT]
    const float* __restrict__ bfeat, // [B, FEAT]
    const float* __restrict__ stm,   // [B, 1]
    const float* __restrict__ ftw,   // [HID, FEAT]
    const float* __restrict__ ft_b)  // [HID]
{
    __shared__ union {
        float tile[64][33];
        struct { int idxW[MAXIDX]; int idxB[MAXIDX]; int cw; int cb; } s;
    } sm;

    const int tid = threadIdx.x;

    if (blockIdx.x < NT) {
        // ---------------- transpose: 40 tiles of 64h x 32f per CTA ----------------
        for (int t = blockIdx.x; t < NTILES; t += NT) {
            const int f0 = (t % NTILE_F) * 32;
            const int h0 = (t / NTILE_F) * 64;
#pragma unroll
            for (int u = 0; u < 8; u++) {
                int idx = tid + u * T1;
                int hl = idx >> 5, fl = idx & 31;
                sm.tile[hl][fl] = __ldcs(ftw + (size_t)(h0 + hl) * FEAT + f0 + fl);
            }
            __syncthreads();
#pragma unroll
            for (int u = 0; u < 4; u++) {
                int idx = tid + u * T1;
                int fl = idx >> 5, hp = idx & 31;
                __half2 v = __floats2half2_rn(sm.tile[2 * hp][fl], sm.tile[2 * hp + 1][fl]);
                *reinterpret_cast<__half2*>(g_ftT + (size_t)(f0 + fl) * HID + h0 + 2 * hp) = v;
            }
            __syncthreads();
        }
        __threadfence();
        __syncthreads();
        if (tid == 0) atomicAdd(&g_done, 1);
        return;
    }

    // ---------------- scan ----------------
    const int b = blockIdx.x - NT;

    if (tid == 0) { sm.s.cw = 0; sm.s.cb = 0; }
    __syncthreads();
    {
        const float4* pw = (const float4*)(wf    + (size_t)b * FEAT);
        const float4* pb = (const float4*)(bfeat + (size_t)b * FEAT);
        for (int base = 0; base < FEAT / 4; base += 4 * T1) {
            float4 v[4], w[4];
#pragma unroll
            for (int u = 0; u < 4; u++) {
                v[u] = __ldcs(pw + base + tid + u * T1);
                w[u] = __ldcs(pb + base + tid + u * T1);
            }
#pragma unroll
            for (int u = 0; u < 4; u++) {
                int i = base + tid + u * T1;
                if (v[u].x != 0.f) { int q = atomicAdd(&sm.s.cw, 1); if (q < MAXIDX) sm.s.idxW[q] = 4*i;   }
                if (v[u].y != 0.f) { int q = atomicAdd(&sm.s.cw, 1); if (q < MAXIDX) sm.s.idxW[q] = 4*i+1; }
                if (v[u].z != 0.f) { int q = atomicAdd(&sm.s.cw, 1); if (q < MAXIDX) sm.s.idxW[q] = 4*i+2; }
                if (v[u].w != 0.f) { int q = atomicAdd(&sm.s.cw, 1); if (q < MAXIDX) sm.s.idxW[q] = 4*i+3; }
                if (w[u].x != 0.f) { int q = atomicAdd(&sm.s.cb, 1); if (q < MAXIDX) sm.s.idxB[q] = 4*i;   }
                if (w[u].y != 0.f) { int q = atomicAdd(&sm.s.cb, 1); if (q < MAXIDX) sm.s.idxB[q] = 4*i+1; }
                if (w[u].z != 0.f) { int q = atomicAdd(&sm.s.cb, 1); if (q < MAXIDX) sm.s.idxB[q] = 4*i+2; }
                if (w[u].w != 0.f) { int q = atomicAdd(&sm.s.cb, 1); if (q < MAXIDX) sm.s.idxB[q] = 4*i+3; }
            }
        }
    }
    __syncthreads();

    // wait for transpose completion
    if (tid == 0) {
        while (atomicAdd(&g_done, 0) < NT) __nanosleep(128);
    }
    __syncthreads();
    __threadfence();

    // ---------------- gather ----------------
    const float4 bias = *reinterpret_cast<const float4*>(ft_b + 4 * tid);
    float4 accW = bias, accB = bias;
    const int nW = min(sm.s.cw, MAXIDX);
#pragma unroll 4
    for (int j = 0; j < nW; j++) {
        const uint2 raw = *reinterpret_cast<const uint2*>(
            g_ftT + (size_t)sm.s.idxW[j] * HID + 4 * tid);
        const float2 lo = __half22float2(*reinterpret_cast<const __half2*>(&raw.x));
        const float2 hi = __half22float2(*reinterpret_cast<const __half2*>(&raw.y));
        accW.x += lo.x; accW.y += lo.y; accW.z += hi.x; accW.w += hi.y;
    }
    const int nB = min(sm.s.cb, MAXIDX);
#pragma unroll 4
    for (int j = 0; j < nB; j++) {
        const uint2 raw = *reinterpret_cast<const uint2*>(
            g_ftT + (size_t)sm.s.idxB[j] * HID + 4 * tid);
        const float2 lo = __half22float2(*reinterpret_cast<const __half2*>(&raw.x));
        const float2 hi = __half22float2(*reinterpret_cast<const __half2*>(&raw.y));
        accB.x += lo.x; accB.y += lo.y; accB.z += hi.x; accB.w += hi.y;
    }

    // stm select + clip + store h1 (fp16)
    const float s = __ldg(stm + b);
    float cw[4] = {fminf(fmaxf(accW.x,0.f),1.f), fminf(fmaxf(accW.y,0.f),1.f),
                   fminf(fmaxf(accW.z,0.f),1.f), fminf(fmaxf(accW.w,0.f),1.f)};
    float cb[4] = {fminf(fmaxf(accB.x,0.f),1.f), fminf(fmaxf(accB.y,0.f),1.f),
                   fminf(fmaxf(accB.z,0.f),1.f), fminf(fmaxf(accB.w,0.f),1.f)};
    __half* o = g_h1 + (size_t)b * HID2;
    uint2 pf, ps;
    *reinterpret_cast<__half2*>(&pf.x) = __floats2half2_rn(
        s*cw[0]+(1.f-s)*cb[0], s*cw[1]+(1.f-s)*cb[1]);
    *reinterpret_cast<__half2*>(&pf.y) = __floats2half2_rn(
        s*cw[2]+(1.f-s)*cb[2], s*cw[3]+(1.f-s)*cb[3]);
    *reinterpret_cast<__half2*>(&ps.x) = __floats2half2_rn(
        s*cb[0]+(1.f-s)*cw[0], s*cb[1]+(1.f-s)*cw[1]);
    *reinterpret_cast<__half2*>(&ps.y) = __floats2half2_rn(
        s*cb[2]+(1.f-s)*cw[2], s*cb[3]+(1.f-s)*cw[3]);
    *reinterpret_cast<uint2*>(o + 4 * tid)       = pf;
    *reinterpret_cast<uint2*>(o + HID + 4 * tid) = ps;

    // ---- self-reset: last scanner restores counters for the next replay ----
    __syncthreads();
    if (tid == 0) {
        int v = atomicAdd(&g_scan_done, 1);
        if (v == BATCH - 1) {        // every scanner (incl. this one) passed the wait
            g_done = 0;
            atomicExch(&g_scan_done, 0);
        }
    }
}

// =========================================================================
// mlp1: l1 partial GEMM. grid = 512 CTAs, T2 = 512 threads (16 warps).
// CTA (grp, q): rows [32*grp, +32), k in [512*q, +512). 2x2 thread tiles.
// h-tile inner load is a warp broadcast (ty == warp id).
// =========================================================================
#define T2    512
#define TB    32
#define CHUNK 64
#define NCHQ  (QK / CHUNK)   // 8
#define HPAD  36
#define WPAD  66

__global__ __launch_bounds__(T2) void mlp1_kernel(const float* __restrict__ l1_w)
{
    __shared__ __align__(16) float hst[2][CHUNK][HPAD];   // 18.4 KB
    __shared__ __align__(16) float wst[2][CHUNK][WPAD];   // 33.8 KB

    const int tid  = threadIdx.x;
    const int grp  = blockIdx.x >> 2;
    const int q    = blockIdx.x & 3;
    const int row0 = grp * TB;
    const int kb   = q * QK;
    const int tx   = tid & 31;   // out pair {2tx, 2tx+1}
    const int ty   = tid >> 5;   // row pair {2ty, 2ty+1}, ty = warp id (0..15)

    __half2 hreg[2];
    float   wreg[8];
    {
#pragma unroll
        for (int u = 0; u < 2; u++) {
            int idx = tid + u * T2; int r = idx >> 5, kp = idx & 31;
            hreg[u] = *reinterpret_cast<const __half2*>(
                g_h1 + (size_t)(row0 + r) * HID2 + kb + 2 * kp);
        }
#pragma unroll
        for (int u = 0; u < 8; u++) {
            int idx = tid + u * T2; int oo = idx >> 6, kk = idx & 63;
            wreg[u] = __ldg(l1_w + (size_t)oo * HID2 + kb + kk);
        }
#pragma unroll
        for (int u = 0; u < 2; u++) {
            int idx = tid + u * T2; int r = idx >> 5, kp = idx & 31;
            float2 f = __half22float2(hreg[u]);
            hst[0][2 * kp][r]     = f.x;
            hst[0][2 * kp + 1][r] = f.y;
        }
#pragma unroll
        for (int u = 0; u < 8; u++) {
            int idx = tid + u * T2; int oo = idx >> 6, kk = idx & 63;
            wst[0][kk][oo] = wreg[u];
        }
    }
    __syncthreads();

    float acc[2][2];
    acc[0][0] = acc[0][1] = acc[1][0] = acc[1][1] = 0.f;

    for (int c = 0; c < NCHQ; c++) {
        const int buf = c & 1;
        if (c + 1 < NCHQ) {
            const int kc = kb + (c + 1) * CHUNK;
#pragma unroll
            for (int u = 0; u < 2; u++) {
                int idx = tid + u * T2; int r = idx >> 5, kp = idx & 31;
                hreg[u] = *reinterpret_cast<const __half2*>(
                    g_h1 + (size_t)(row0 + r) * HID2 + kc + 2 * kp);
            }
#pragma unroll
            for (int u = 0; u < 8; u++) {
                int idx = tid + u * T2; int oo = idx >> 6, kk = idx & 63;
                wreg[u] = __ldg(l1_w + (size_t)oo * HID2 + kc + kk);
            }
        }
#pragma unroll 16
        for (int k = 0; k < CHUNK; k++) {
            const float2 h = *reinterpret_cast<const float2*>(&hst[buf][k][2 * ty]);
            const float2 w = *reinterpret_cast<const float2*>(&wst[buf][k][2 * tx]);
            acc[0][0] = fmaf(h.x, w.x, acc[0][0]); acc[0][1] = fmaf(h.x, w.y, acc[0][1]);
            acc[1][0] = fmaf(h.y, w.x, acc[1][0]); acc[1][1] = fmaf(h.y, w.y, acc[1][1]);
        }
        if (c + 1 < NCHQ) {
            const int nb = (c + 1) & 1;
#pragma unroll
            for (int u = 0; u < 2; u++) {
                int idx = tid + u * T2; int r = idx >> 5, kp = idx & 31;
                float2 f = __half22float2(hreg[u]);
                hst[nb][2 * kp][r]     = f.x;
                hst[nb][2 * kp + 1][r] = f.y;
            }
#pragma unroll
            for (int u = 0; u < 8; u++) {
                int idx = tid + u * T2; int oo = idx >> 6, kk = idx & 63;
                wst[nb][kk][oo] = wreg[u];
            }
        }
        __syncthreads();
    }

    // store partials: g_part[q][grp][row][out]
    float* dst = g_part + (((size_t)q * NGRP + grp) * TB) * NL1;
#pragma unroll
    for (int i = 0; i < 2; i++) {
        float2 v = make_float2(acc[i][0], acc[i][1]);
        *reinterpret_cast<float2*>(dst + (2 * ty + i) * NL1 + 2 * tx) = v;
    }
}

// =========================================================================
// mlp2: reduce partials + bias + clip -> l2 -> l3 -> sigmoid.
// grid = 512 CTAs x 8 rows, 256 threads (latency-bound -> spread wide).
// =========================================================================
#define T3    256
#define RB    8                 // rows per mlp2 CTA
__global__ __launch_bounds__(T3) void mlp2_kernel(
    const float* __restrict__ l1_b,
    const float* __restrict__ l2_w, const float* __restrict__ l2_b,
    const float* __restrict__ l3_w, const float* __restrict__ l3_b,
    float* __restrict__ out, int out_size)
{
    __shared__ float h2s[RB][NL1 + 1];
    __shared__ float h3s[RB][NL2 + 1];
    __shared__ float l2s[NL2][NL1 + 1];

    const int tid  = threadIdx.x;
    const int row0 = blockIdx.x * RB;            // global row base
    const int grp  = row0 >> 5;                  // owning group
    const int rg0  = row0 & 31;                  // row offset inside group

    for (int i = tid; i < NL2 * NL1; i += T3) l2s[i >> 6][i & 63] = l2_w[i];

    // reduce quarters + bias + clip: RB*NL1 = 512 entries -> 2/thread
    const float* base = g_part + ((size_t)grp * TB + rg0) * NL1;
    for (int p = tid; p < RB * NL1; p += T3) {
        int r = p >> 6, o = p & 63;
        float s = __ldg(l1_b + o);
#pragma unroll
        for (int q = 0; q < NQ; q++)
            s += base[(size_t)q * NGRP * TB * NL1 + r * NL1 + o];
        h2s[r][o] = fminf(fmaxf(s, 0.f), 1.f);
    }
    __syncthreads();

    // l2: RB x 32 = 256 -> 1/thread
    for (int p = tid; p < RB * NL2; p += T3) {
        int r = p >> 5, oo = p & 31;
        float s = __ldg(l2_b + oo);
#pragma unroll
        for (int k = 0; k < NL1; k++) s = fmaf(h2s[r][k], l2s[oo][k], s);
        h3s[r][oo] = fminf(fmaxf(s, 0.f), 1.f);
    }
    __syncthreads();

    // l3 + sigmoid
    if (tid < RB) {
        float s = __ldg(l3_b);
#pragma unroll
        for (int k = 0; k < NL2; k++) s = fmaf(h3s[tid][k], __ldg(l3_w + k), s);
        float sig = 1.f / (1.f + expf(-s));
        int r = row0 + tid;
        if (out_size >= 2 * BATCH) {
            out[r]         = sig;
            out[BATCH + r] = s;
        } else {
            out[r] = sig;
        }
    }
}

// =========================================================================
extern "C" void kernel_launch(void* const* d_in, const int* in_sizes, int n_in,
                              void* d_out, int out_size)
{
    const float* wf    = (const float*)d_in[0];
    const float* bfeat = (const float*)d_in[1];
    const float* stm   = (const float*)d_in[2];
    const float* ft_w  = (const float*)d_in[3];
    const float* ft_b  = (const float*)d_in[4];
    const float* l1_w  = (const float*)d_in[5];
    const float* l1_b  = (const float*)d_in[6];
    const float* l2_w  = (const float*)d_in[7];
    const float* l2_b  = (const float*)d_in[8];
    const float* l3_w  = (const float*)d_in[9];
    const float* l3_b  = (const float*)d_in[10];
    float* out = (float*)d_out;

    mega_kernel<<<NT + BATCH, T1>>>(wf, bfeat, stm, ft_w, ft_b);
    mlp1_kernel<<<NGRP * NQ, T2>>>(l1_w);
    mlp2_kernel<<<BATCH / RB, T3>>>(l1_b, l2_w, l2_b, l3_w, l3_b, out, out_size);
}

// round 14
// speedup vs baseline: 1.0382x; 1.0382x over previous
#include <cuda_runtime.h>
#include <cuda_fp16.h>
#include <math.h>

#define BATCH 4096
#define FEAT  40960
#define HID   1024
#define HID2  2048
#define NL1   64
#define NL2   32
#define GRP   32
#define NGRP  (BATCH / GRP)     // 128
#define NQ    4                 // k-quarters
#define QK    (HID2 / NQ)       // 512

// ---------------- static device scratch (no allocs allowed) ----------------
__device__ __half g_ftT[(size_t)FEAT * HID];             // 83.9 MB
__device__ __half g_h1[(size_t)BATCH * HID2];            // 16.8 MB
__device__ float  g_part[(size_t)NQ * NGRP * GRP * NL1]; // 4.2 MB l1 partials
__device__ int    g_done;        // transpose completion (self-resetting)
__device__ int    g_scan_done;   // scanner completion (self-resetting)

// =========================================================================
// Mega-kernel (proven: 291.6us, regs 40, DRAM 73.6%):
//   CTAs [0, NT)        : transpose ft_w -> g_ftT (fp16), signal.
//   CTAs [NT, NT+BATCH) : scan -> wait -> gather -> h1 (fp16).
// Last scanner CTA resets both counters (all waits already passed), so no
// separate reset launch is needed and graph replays stay correct.
// =========================================================================
#define T1      256
#define NT      512
#define MAXIDX  256
#define NTILE_F (FEAT / 32)                 // 1280
#define NTILES  (NTILE_F * (HID / 64))      // 20480

__global__ __launch_bounds__(T1) void mega_kernel(
    const float* __restrict__ wf,    // [B, FEAT]
    const float* __restrict__ bfeat, // [B, FEAT]
    const float* __restrict__ stm,   // [B, 1]
    const float* __restrict__ ftw,   // [HID, FEAT]
    const float* __restrict__ ft_b)  // [HID]
{
    __shared__ union {
        float tile[64][33];
        struct { int idxW[MAXIDX]; int idxB[MAXIDX]; int cw; int cb; } s;
    } sm;

    const int tid = threadIdx.x;

    if (blockIdx.x < NT) {
        // ---------------- transpose: 40 tiles of 64h x 32f per CTA ----------------
        for (int t = blockIdx.x; t < NTILES; t += NT) {
            const int f0 = (t % NTILE_F) * 32;
            const int h0 = (t / NTILE_F) * 64;
#pragma unroll
            for (int u = 0; u < 8; u++) {
                int idx = tid + u * T1;
                int hl = idx >> 5, fl = idx & 31;
                sm.tile[hl][fl] = __ldcs(ftw + (size_t)(h0 + hl) * FEAT + f0 + fl);
            }
            __syncthreads();
#pragma unroll
            for (int u = 0; u < 4; u++) {
                int idx = tid + u * T1;
                int fl = idx >> 5, hp = idx & 31;
                __half2 v = __floats2half2_rn(sm.tile[2 * hp][fl], sm.tile[2 * hp + 1][fl]);
                *reinterpret_cast<__half2*>(g_ftT + (size_t)(f0 + fl) * HID + h0 + 2 * hp) = v;
            }
            __syncthreads();
        }
        __threadfence();
        __syncthreads();
        if (tid == 0) atomicAdd(&g_done, 1);
        return;
    }

    // ---------------- scan ----------------
    const int b = blockIdx.x - NT;

    if (tid == 0) { sm.s.cw = 0; sm.s.cb = 0; }
    __syncthreads();
    {
        const float4* pw = (const float4*)(wf    + (size_t)b * FEAT);
        const float4* pb = (const float4*)(bfeat + (size_t)b * FEAT);
        for (int base = 0; base < FEAT / 4; base += 4 * T1) {
            float4 v[4], w[4];
#pragma unroll
            for (int u = 0; u < 4; u++) {
                v[u] = __ldcs(pw + base + tid + u * T1);
                w[u] = __ldcs(pb + base + tid + u * T1);
            }
#pragma unroll
            for (int u = 0; u < 4; u++) {
                int i = base + tid + u * T1;
                if (v[u].x != 0.f) { int q = atomicAdd(&sm.s.cw, 1); if (q < MAXIDX) sm.s.idxW[q] = 4*i;   }
                if (v[u].y != 0.f) { int q = atomicAdd(&sm.s.cw, 1); if (q < MAXIDX) sm.s.idxW[q] = 4*i+1; }
                if (v[u].z != 0.f) { int q = atomicAdd(&sm.s.cw, 1); if (q < MAXIDX) sm.s.idxW[q] = 4*i+2; }
                if (v[u].w != 0.f) { int q = atomicAdd(&sm.s.cw, 1); if (q < MAXIDX) sm.s.idxW[q] = 4*i+3; }
                if (w[u].x != 0.f) { int q = atomicAdd(&sm.s.cb, 1); if (q < MAXIDX) sm.s.idxB[q] = 4*i;   }
                if (w[u].y != 0.f) { int q = atomicAdd(&sm.s.cb, 1); if (q < MAXIDX) sm.s.idxB[q] = 4*i+1; }
                if (w[u].z != 0.f) { int q = atomicAdd(&sm.s.cb, 1); if (q < MAXIDX) sm.s.idxB[q] = 4*i+2; }
                if (w[u].w != 0.f) { int q = atomicAdd(&sm.s.cb, 1); if (q < MAXIDX) sm.s.idxB[q] = 4*i+3; }
            }
        }
    }
    __syncthreads();

    // wait for transpose completion
    if (tid == 0) {
        while (atomicAdd(&g_done, 0) < NT) __nanosleep(128);
    }
    __syncthreads();
    __threadfence();

    // ---------------- gather ----------------
    const float4 bias = *reinterpret_cast<const float4*>(ft_b + 4 * tid);
    float4 accW = bias, accB = bias;
    const int nW = min(sm.s.cw, MAXIDX);
#pragma unroll 4
    for (int j = 0; j < nW; j++) {
        const uint2 raw = *reinterpret_cast<const uint2*>(
            g_ftT + (size_t)sm.s.idxW[j] * HID + 4 * tid);
        const float2 lo = __half22float2(*reinterpret_cast<const __half2*>(&raw.x));
        const float2 hi = __half22float2(*reinterpret_cast<const __half2*>(&raw.y));
        accW.x += lo.x; accW.y += lo.y; accW.z += hi.x; accW.w += hi.y;
    }
    const int nB = min(sm.s.cb, MAXIDX);
#pragma unroll 4
    for (int j = 0; j < nB; j++) {
        const uint2 raw = *reinterpret_cast<const uint2*>(
            g_ftT + (size_t)sm.s.idxB[j] * HID + 4 * tid);
        const float2 lo = __half22float2(*reinterpret_cast<const __half2*>(&raw.x));
        const float2 hi = __half22float2(*reinterpret_cast<const __half2*>(&raw.y));
        accB.x += lo.x; accB.y += lo.y; accB.z += hi.x; accB.w += hi.y;
    }

    // stm select + clip + store h1 (fp16)
    const float s = __ldg(stm + b);
    float cw[4] = {fminf(fmaxf(accW.x,0.f),1.f), fminf(fmaxf(accW.y,0.f),1.f),
                   fminf(fmaxf(accW.z,0.f),1.f), fminf(fmaxf(accW.w,0.f),1.f)};
    float cb[4] = {fminf(fmaxf(accB.x,0.f),1.f), fminf(fmaxf(accB.y,0.f),1.f),
                   fminf(fmaxf(accB.z,0.f),1.f), fminf(fmaxf(accB.w,0.f),1.f)};
    __half* o = g_h1 + (size_t)b * HID2;
    uint2 pf, ps;
    *reinterpret_cast<__half2*>(&pf.x) = __floats2half2_rn(
        s*cw[0]+(1.f-s)*cb[0], s*cw[1]+(1.f-s)*cb[1]);
    *reinterpret_cast<__half2*>(&pf.y) = __floats2half2_rn(
        s*cw[2]+(1.f-s)*cb[2], s*cw[3]+(1.f-s)*cb[3]);
    *reinterpret_cast<__half2*>(&ps.x) = __floats2half2_rn(
        s*cb[0]+(1.f-s)*cw[0], s*cb[1]+(1.f-s)*cw[1]);
    *reinterpret_cast<__half2*>(&ps.y) = __floats2half2_rn(
        s*cb[2]+(1.f-s)*cw[2], s*cb[3]+(1.f-s)*cw[3]);
    *reinterpret_cast<uint2*>(o + 4 * tid)       = pf;
    *reinterpret_cast<uint2*>(o + HID + 4 * tid) = ps;

    // ---- self-reset: last scanner restores counters for the next replay ----
    __syncthreads();
    if (tid == 0) {
        int v = atomicAdd(&g_scan_done, 1);
        if (v == BATCH - 1) {
            g_done = 0;
            atomicExch(&g_scan_done, 0);
        }
    }
}

// =========================================================================
// mlp1 (R11 proven, ~33us): grid = NGRP*NQ = 512 CTAs, 256 threads.
// CTA (grp, q): rows [32*grp, +32), k in [512*q, +512). 4x2 thread tiles.
// =========================================================================
#define T2    256
#define TB    32
#define CHUNK 64
#define NCHQ  (QK / CHUNK)   // 8
#define HPAD  36
#define WPAD  66

__global__ __launch_bounds__(T2) void mlp1_kernel(const float* __restrict__ l1_w)
{
    __shared__ __align__(16) float hst[2][CHUNK][HPAD];   // 18.4 KB
    __shared__ __align__(16) float wst[2][CHUNK][WPAD];   // 33.8 KB

    const int tid  = threadIdx.x;
    const int grp  = blockIdx.x >> 2;
    const int q    = blockIdx.x & 3;
    const int row0 = grp * TB;
    const int kb   = q * QK;
    const int tx   = tid & 31;   // out pair {2tx, 2tx+1}
    const int ty   = tid >> 5;   // row quad {4ty..4ty+3}

    __half2 hreg[4];
    float   wreg[16];
    {
#pragma unroll
        for (int u = 0; u < 4; u++) {
            int idx = tid + u * T2; int r = idx >> 5, kp = idx & 31;
            hreg[u] = *reinterpret_cast<const __half2*>(
                g_h1 + (size_t)(row0 + r) * HID2 + kb + 2 * kp);
        }
#pragma unroll
        for (int u = 0; u < 16; u++) {
            int idx = tid + u * T2; int oo = idx >> 6, kk = idx & 63;
            wreg[u] = __ldg(l1_w + (size_t)oo * HID2 + kb + kk);
        }
#pragma unroll
        for (int u = 0; u < 4; u++) {
            int idx = tid + u * T2; int r = idx >> 5, kp = idx & 31;
            float2 f = __half22float2(hreg[u]);
            hst[0][2 * kp][r]     = f.x;
            hst[0][2 * kp + 1][r] = f.y;
        }
#pragma unroll
        for (int u = 0; u < 16; u++) {
            int idx = tid + u * T2; int oo = idx >> 6, kk = idx & 63;
            wst[0][kk][oo] = wreg[u];
        }
    }
    __syncthreads();

    float acc[4][2];
#pragma unroll
    for (int i = 0; i < 4; i++) { acc[i][0] = 0.f; acc[i][1] = 0.f; }

    for (int c = 0; c < NCHQ; c++) {
        const int buf = c & 1;
        if (c + 1 < NCHQ) {
            const int kc = kb + (c + 1) * CHUNK;
#pragma unroll
            for (int u = 0; u < 4; u++) {
                int idx = tid + u * T2; int r = idx >> 5, kp = idx & 31;
                hreg[u] = *reinterpret_cast<const __half2*>(
                    g_h1 + (size_t)(row0 + r) * HID2 + kc + 2 * kp);
            }
#pragma unroll
            for (int u = 0; u < 16; u++) {
                int idx = tid + u * T2; int oo = idx >> 6, kk = idx & 63;
                wreg[u] = __ldg(l1_w + (size_t)oo * HID2 + kc + kk);
            }
        }
#pragma unroll 16
        for (int k = 0; k < CHUNK; k++) {
            const float4 h = *reinterpret_cast<const float4*>(&hst[buf][k][4 * ty]);
            const float2 w = *reinterpret_cast<const float2*>(&wst[buf][k][2 * tx]);
            acc[0][0] = fmaf(h.x, w.x, acc[0][0]); acc[0][1] = fmaf(h.x, w.y, acc[0][1]);
            acc[1][0] = fmaf(h.y, w.x, acc[1][0]); acc[1][1] = fmaf(h.y, w.y, acc[1][1]);
            acc[2][0] = fmaf(h.z, w.x, acc[2][0]); acc[2][1] = fmaf(h.z, w.y, acc[2][1]);
            acc[3][0] = fmaf(h.w, w.x, acc[3][0]); acc[3][1] = fmaf(h.w, w.y, acc[3][1]);
        }
        if (c + 1 < NCHQ) {
            const int nb = (c + 1) & 1;
#pragma unroll
            for (int u = 0; u < 4; u++) {
                int idx = tid + u * T2; int r = idx >> 5, kp = idx & 31;
                float2 f = __half22float2(hreg[u]);
                hst[nb][2 * kp][r]     = f.x;
                hst[nb][2 * kp + 1][r] = f.y;
            }
#pragma unroll
            for (int u = 0; u < 16; u++) {
                int idx = tid + u * T2; int oo = idx >> 6, kk = idx & 63;
                wst[nb][kk][oo] = wreg[u];
            }
        }
        __syncthreads();
    }

    // store partials: g_part[q][grp][row][out]
    float* dst = g_part + (((size_t)q * NGRP + grp) * TB) * NL1;
#pragma unroll
    for (int i = 0; i < 4; i++) {
        float2 v = make_float2(acc[i][0], acc[i][1]);
        *reinterpret_cast<float2*>(dst + (4 * ty + i) * NL1 + 2 * tx) = v;
    }
}

// =========================================================================
// mlp2 (R11 proven, ~14us): reduce partials + bias + clip -> l2 -> l3 ->
// sigmoid. 128 CTAs x 32 rows, 256 threads.
// =========================================================================
__global__ __launch_bounds__(T2) void mlp2_kernel(
    const float* __restrict__ l1_b,
    const float* __restrict__ l2_w, const float* __restrict__ l2_b,
    const float* __restrict__ l3_w, const float* __restrict__ l3_b,
    float* __restrict__ out, int out_size)
{
    __shared__ float h2s[GRP][NL1 + 1];
    __shared__ float h3s[GRP][NL2 + 1];
    __shared__ float l2s[NL2][NL1 + 1];

    const int tid = threadIdx.x;
    const int grp = blockIdx.x;
    const int row0 = grp * GRP;

    for (int i = tid; i < NL2 * NL1; i += T2) l2s[i >> 6][i & 63] = l2_w[i];

    // sum 4 quarters + bias, clip -> h2s  (2048 entries, 8/thread)
    const float* base = g_part + (size_t)grp * TB * NL1;
    for (int p = tid; p < GRP * NL1; p += T2) {
        int r = p >> 6, o = p & 63;
        float s = __ldg(l1_b + o);
#pragma unroll
        for (int q = 0; q < NQ; q++)
            s += base[(size_t)q * NGRP * TB * NL1 + r * NL1 + o];
        h2s[r][o] = fminf(fmaxf(s, 0.f), 1.f);
    }
    __syncthreads();

    // l2: 32 rows x 32 outs = 1024 -> 4/thread
    for (int p = tid; p < GRP * NL2; p += T2) {
        int r = p >> 5, oo = p & 31;
        float s = __ldg(l2_b + oo);
#pragma unroll
        for (int k = 0; k < NL1; k++) s = fmaf(h2s[r][k], l2s[oo][k], s);
        h3s[r][oo] = fminf(fmaxf(s, 0.f), 1.f);
    }
    __syncthreads();

    // l3 + sigmoid
    if (tid < GRP) {
        float s = __ldg(l3_b);
#pragma unroll
        for (int k = 0; k < NL2; k++) s = fmaf(h3s[tid][k], __ldg(l3_w + k), s);
        float sig = 1.f / (1.f + expf(-s));
        int r = row0 + tid;
        if (out_size >= 2 * BATCH) {
            out[r]         = sig;
            out[BATCH + r] = s;
        } else {
            out[r] = sig;
        }
    }
}

// =========================================================================
extern "C" void kernel_launch(void* const* d_in, const int* in_sizes, int n_in,
                              void* d_out, int out_size)
{
    const float* wf    = (const float*)d_in[0];
    const float* bfeat = (const float*)d_in[1];
    const float* stm   = (const float*)d_in[2];
    const float* ft_w  = (const float*)d_in[3];
    const float* ft_b  = (const float*)d_in[4];
    const float* l1_w  = (const float*)d_in[5];
    const float* l1_b  = (const float*)d_in[6];
    const float* l2_w  = (const float*)d_in[7];
    const float* l2_b  = (const float*)d_in[8];
    const float* l3_w  = (const float*)d_in[9];
    const float* l3_b  = (const float*)d_in[10];
    float* out = (float*)d_out;

    mega_kernel<<<NT + BATCH, T1>>>(wf, bfeat, stm, ft_w, ft_b);
    mlp1_kernel<<<NGRP * NQ, T2>>>(l1_w);
    mlp2_kernel<<<NGRP, T2>>>(l1_b, l2_w, l2_b, l3_w, l3_b, out, out_size);
}

// round 15
// speedup vs baseline: 1.0428x; 1.0045x over previous
#include <cuda_runtime.h>
#include <cuda_fp16.h>
#include <mma.h>
#include <math.h>

using namespace nvcuda;

#define BATCH 4096
#define FEAT  40960
#define HID   1024
#define HID2  2048
#define NL1   64
#define NL2   32
#define GRP   32
#define NGRP  (BATCH / GRP)     // 128

// ---------------- static device scratch (no allocs allowed) ----------------
__device__ __half g_ftT[(size_t)FEAT * HID];    // 83.9 MB
__device__ __half g_h1[(size_t)BATCH * HID2];   // 16.8 MB
__device__ __half g_l1w[(size_t)NL1 * HID2];    // 256 KB: l1_w fp16
__device__ int    g_done;        // transpose completion (self-resetting)
__device__ int    g_scan_done;   // scanner completion (self-resetting)

// =========================================================================
// Mega-kernel (proven: ~292us, regs 40, DRAM 73.4%):
//   CTAs [0, NT)        : transpose ft_w -> g_ftT (fp16); CTAs [0,128) also
//                         convert l1_w -> fp16; signal g_done.
//   CTAs [NT, NT+BATCH) : scan -> wait -> gather -> h1 (fp16).
// Last scanner CTA resets both counters (all waits already passed).
// =========================================================================
#define T1      256
#define NT      512
#define MAXIDX  256
#define NTILE_F (FEAT / 32)                 // 1280
#define NTILES  (NTILE_F * (HID / 64))      // 20480

__global__ __launch_bounds__(T1) void mega_kernel(
    const float* __restrict__ wf,    // [B, FEAT]
    const float* __restrict__ bfeat, // [B, FEAT]
    const float* __restrict__ stm,   // [B, 1]
    const float* __restrict__ ftw,   // [HID, FEAT]
    const float* __restrict__ ft_b,  // [HID]
    const float* __restrict__ l1_w)  // [64, 2048]
{
    __shared__ union {
        float tile[64][33];
        struct { int idxW[MAXIDX]; int idxB[MAXIDX]; int cw; int cb; } s;
    } sm;

    const int tid = threadIdx.x;

    if (blockIdx.x < NT) {
        // ---------------- transpose: 40 tiles of 64h x 32f per CTA ----------------
        for (int t = blockIdx.x; t < NTILES; t += NT) {
            const int f0 = (t % NTILE_F) * 32;
            const int h0 = (t / NTILE_F) * 64;
#pragma unroll
            for (int u = 0; u < 8; u++) {
                int idx = tid + u * T1;
                int hl = idx >> 5, fl = idx & 31;
                sm.tile[hl][fl] = __ldcs(ftw + (size_t)(h0 + hl) * FEAT + f0 + fl);
            }
            __syncthreads();
#pragma unroll
            for (int u = 0; u < 4; u++) {
                int idx = tid + u * T1;
                int fl = idx >> 5, hp = idx & 31;
                __half2 v = __floats2half2_rn(sm.tile[2 * hp][fl], sm.tile[2 * hp + 1][fl]);
                *reinterpret_cast<__half2*>(g_ftT + (size_t)(f0 + fl) * HID + h0 + 2 * hp) = v;
            }
            __syncthreads();
        }
        // ---- CTAs [0,128): convert l1_w (64x2048 = 131072 floats) to fp16 ----
        if (blockIdx.x < 128) {
            const int base = blockIdx.x * 1024 + tid * 4;  // 4 consecutive per thread
            float4 v = *reinterpret_cast<const float4*>(l1_w + base);
            __half2 lo = __floats2half2_rn(v.x, v.y);
            __half2 hi = __floats2half2_rn(v.z, v.w);
            *reinterpret_cast<__half2*>(g_l1w + base)     = lo;
            *reinterpret_cast<__half2*>(g_l1w + base + 2) = hi;
        }
        __threadfence();
        __syncthreads();
        if (tid == 0) atomicAdd(&g_done, 1);
        return;
    }

    // ---------------- scan ----------------
    const int b = blockIdx.x - NT;

    if (tid == 0) { sm.s.cw = 0; sm.s.cb = 0; }
    __syncthreads();
    {
        const float4* pw = (const float4*)(wf    + (size_t)b * FEAT);
        const float4* pb = (const float4*)(bfeat + (size_t)b * FEAT);
        for (int base = 0; base < FEAT / 4; base += 4 * T1) {
            float4 v[4], w[4];
#pragma unroll
            for (int u = 0; u < 4; u++) {
                v[u] = __ldcs(pw + base + tid + u * T1);
                w[u] = __ldcs(pb + base + tid + u * T1);
            }
#pragma unroll
            for (int u = 0; u < 4; u++) {
                int i = base + tid + u * T1;
                if (v[u].x != 0.f) { int q = atomicAdd(&sm.s.cw, 1); if (q < MAXIDX) sm.s.idxW[q] = 4*i;   }
                if (v[u].y != 0.f) { int q = atomicAdd(&sm.s.cw, 1); if (q < MAXIDX) sm.s.idxW[q] = 4*i+1; }
                if (v[u].z != 0.f) { int q = atomicAdd(&sm.s.cw, 1); if (q < MAXIDX) sm.s.idxW[q] = 4*i+2; }
                if (v[u].w != 0.f) { int q = atomicAdd(&sm.s.cw, 1); if (q < MAXIDX) sm.s.idxW[q] = 4*i+3; }
                if (w[u].x != 0.f) { int q = atomicAdd(&sm.s.cb, 1); if (q < MAXIDX) sm.s.idxB[q] = 4*i;   }
                if (w[u].y != 0.f) { int q = atomicAdd(&sm.s.cb, 1); if (q < MAXIDX) sm.s.idxB[q] = 4*i+1; }
                if (w[u].z != 0.f) { int q = atomicAdd(&sm.s.cb, 1); if (q < MAXIDX) sm.s.idxB[q] = 4*i+2; }
                if (w[u].w != 0.f) { int q = atomicAdd(&sm.s.cb, 1); if (q < MAXIDX) sm.s.idxB[q] = 4*i+3; }
            }
        }
    }
    __syncthreads();

    // wait for transpose (+ l1w conversion) completion
    if (tid == 0) {
        while (atomicAdd(&g_done, 0) < NT) __nanosleep(128);
    }
    __syncthreads();
    __threadfence();

    // ---------------- gather ----------------
    const float4 bias = *reinterpret_cast<const float4*>(ft_b + 4 * tid);
    float4 accW = bias, accB = bias;
    const int nW = min(sm.s.cw, MAXIDX);
#pragma unroll 4
    for (int j = 0; j < nW; j++) {
        const uint2 raw = *reinterpret_cast<const uint2*>(
            g_ftT + (size_t)sm.s.idxW[j] * HID + 4 * tid);
        const float2 lo = __half22float2(*reinterpret_cast<const __half2*>(&raw.x));
        const float2 hi = __half22float2(*reinterpret_cast<const __half2*>(&raw.y));
        accW.x += lo.x; accW.y += lo.y; accW.z += hi.x; accW.w += hi.y;
    }
    const int nB = min(sm.s.cb, MAXIDX);
#pragma unroll 4
    for (int j = 0; j < nB; j++) {
        const uint2 raw = *reinterpret_cast<const uint2*>(
            g_ftT + (size_t)sm.s.idxB[j] * HID + 4 * tid);
        const float2 lo = __half22float2(*reinterpret_cast<const __half2*>(&raw.x));
        const float2 hi = __half22float2(*reinterpret_cast<const __half2*>(&raw.y));
        accB.x += lo.x; accB.y += lo.y; accB.z += hi.x; accB.w += hi.y;
    }

    // stm select + clip + store h1 (fp16)
    const float s = __ldg(stm + b);
    float cw[4] = {fminf(fmaxf(accW.x,0.f),1.f), fminf(fmaxf(accW.y,0.f),1.f),
                   fminf(fmaxf(accW.z,0.f),1.f), fminf(fmaxf(accW.w,0.f),1.f)};
    float cb[4] = {fminf(fmaxf(accB.x,0.f),1.f), fminf(fmaxf(accB.y,0.f),1.f),
                   fminf(fmaxf(accB.z,0.f),1.f), fminf(fmaxf(accB.w,0.f),1.f)};
    __half* o = g_h1 + (size_t)b * HID2;
    uint2 pf, ps;
    *reinterpret_cast<__half2*>(&pf.x) = __floats2half2_rn(
        s*cw[0]+(1.f-s)*cb[0], s*cw[1]+(1.f-s)*cb[1]);
    *reinterpret_cast<__half2*>(&pf.y) = __floats2half2_rn(
        s*cw[2]+(1.f-s)*cb[2], s*cw[3]+(1.f-s)*cb[3]);
    *reinterpret_cast<__half2*>(&ps.x) = __floats2half2_rn(
        s*cb[0]+(1.f-s)*cw[0], s*cb[1]+(1.f-s)*cw[1]);
    *reinterpret_cast<__half2*>(&ps.y) = __floats2half2_rn(
        s*cb[2]+(1.f-s)*cw[2], s*cb[3]+(1.f-s)*cw[3]);
    *reinterpret_cast<uint2*>(o + 4 * tid)       = pf;
    *reinterpret_cast<uint2*>(o + HID + 4 * tid) = ps;

    // ---- self-reset: last scanner restores counters for the next replay ----
    __syncthreads();
    if (tid == 0) {
        int v = atomicAdd(&g_scan_done, 1);
        if (v == BATCH - 1) {
            g_done = 0;
            atomicExch(&g_scan_done, 0);
        }
    }
}

// =========================================================================
// Tensor-core MLP: 128 CTAs x 256 threads (8 warps).
// Warp w owns output tile [16 rows x 16 outs]: mr = w&1, nc = w>>1.
// l1 via wmma m16n16k16 (fp16 in, fp32 accum), fragments straight from
// global (h1 + l1w are L2-hot). Epilogue (bias/clip/l2/l3/sigmoid) in-CTA.
// =========================================================================
#define T2 256

__global__ __launch_bounds__(T2) void mlp_kernel(
    const float* __restrict__ l1_b,
    const float* __restrict__ l2_w, const float* __restrict__ l2_b,
    const float* __restrict__ l3_w, const float* __restrict__ l3_b,
    float* __restrict__ out, int out_size)
{
    __shared__ float h2s[GRP][72];          // wmma store target (ldm 72), 9.2 KB
    __shared__ float h3s[GRP][NL2 + 1];
    __shared__ float l2s[NL2][NL1 + 1];

    const int tid  = threadIdx.x;
    const int wid  = tid >> 5;
    const int row0 = blockIdx.x * GRP;
    const int mr   = wid & 1;               // 16-row tile: 0..1
    const int nc   = wid >> 1;              // 16-out tile: 0..3

    for (int i = tid; i < NL2 * NL1; i += T2) l2s[i >> 6][i & 63] = l2_w[i];

    // ---- l1 GEMM: [16x2048] x [2048x16] per warp, wmma k16 steps ----
    wmma::fragment<wmma::accumulator, 16, 16, 16, float> c;
    wmma::fill_fragment(c, 0.f);

    const __half* aBase = g_h1 + (size_t)(row0 + mr * 16) * HID2;
    const __half* bBase = g_l1w + (size_t)(nc * 16) * HID2;

#pragma unroll 4
    for (int k = 0; k < HID2; k += 16) {
        wmma::fragment<wmma::matrix_a, 16, 16, 16, __half, wmma::row_major> a;
        wmma::fragment<wmma::matrix_b, 16, 16, 16, __half, wmma::col_major> bfr;
        wmma::load_matrix_sync(a, aBase + k, HID2);
        wmma::load_matrix_sync(bfr, bBase + k, HID2);
        wmma::mma_sync(c, a, bfr, c);
    }
    wmma::store_matrix_sync(&h2s[mr * 16][nc * 16], c, 72, wmma::mem_row_major);
    __syncthreads();

    // ---- bias + clip (in place) ----
    for (int p = tid; p < GRP * NL1; p += T2) {
        int r = p >> 6, o = p & 63;
        float v = h2s[r][o] + __ldg(l1_b + o);
        h2s[r][o] = fminf(fmaxf(v, 0.f), 1.f);
    }
    __syncthreads();

    // ---- l2: 32 rows x 32 outs = 1024 -> 4/thread ----
    for (int p = tid; p < GRP * NL2; p += T2) {
        int r = p >> 5, oo = p & 31;
        float s = __ldg(l2_b + oo);
#pragma unroll
        for (int k = 0; k < NL1; k++) s = fmaf(h2s[r][k], l2s[oo][k], s);
        h3s[r][oo] = fminf(fmaxf(s, 0.f), 1.f);
    }
    __syncthreads();

    // ---- l3 + sigmoid ----
    if (tid < GRP) {
        float s = __ldg(l3_b);
#pragma unroll
        for (int k = 0; k < NL2; k++) s = fmaf(h3s[tid][k], __ldg(l3_w + k), s);
        float sig = 1.f / (1.f + expf(-s));
        int r = row0 + tid;
        if (out_size >= 2 * BATCH) {
            out[r]         = sig;
            out[BATCH + r] = s;
        } else {
            out[r] = sig;
        }
    }
}

// =========================================================================
extern "C" void kernel_launch(void* const* d_in, const int* in_sizes, int n_in,
                              void* d_out, int out_size)
{
    const float* wf    = (const float*)d_in[0];
    const float* bfeat = (const float*)d_in[1];
    const float* stm   = (const float*)d_in[2];
    const float* ft_w  = (const float*)d_in[3];
    const float* ft_b  = (const float*)d_in[4];
    const float* l1_w  = (const float*)d_in[5];
    const float* l1_b  = (const float*)d_in[6];
    const float* l2_w  = (const float*)d_in[7];
    const float* l2_b  = (const float*)d_in[8];
    const float* l3_w  = (const float*)d_in[9];
    const float* l3_b  = (const float*)d_in[10];
    float* out = (float*)d_out;

    mega_kernel<<<NT + BATCH, T1>>>(wf, bfeat, stm, ft_w, ft_b, l1_w);
    mlp_kernel<<<NGRP, T2>>>(l1_b, l2_w, l2_b, l3_w, l3_b, out, out_size);
}

// round 16
// speedup vs baseline: 1.1398x; 1.0930x over previous
#include <cuda_runtime.h>
#include <cuda_fp16.h>
#include <mma.h>
#include <math.h>

using namespace nvcuda;

#define BATCH 4096
#define FEAT  40960
#define HID   1024
#define HID2  2048
#define NL1   64
#define NL2   32
#define GRP   32
#define NGRP  (BATCH / GRP)     // 128

// ---------------- static device scratch (no allocs allowed) ----------------
__device__ __half g_ftT[(size_t)FEAT * HID];    // 83.9 MB
__device__ __half g_h1[(size_t)BATCH * HID2];   // 16.8 MB
__device__ __half g_l1w[(size_t)NL1 * HID2];    // 256 KB: l1_w fp16
__device__ int    g_done;        // transpose completion (self-resetting)
__device__ int    g_scan_done;   // scanner completion (self-resetting)

// =========================================================================
// Mega-kernel (R15 verbatim):
//   CTAs [0, NT)        : transpose ft_w -> g_ftT (fp16); CTAs [0,128) also
//                         convert l1_w -> fp16; signal g_done.
//   CTAs [NT, NT+BATCH) : scan -> wait -> gather -> h1 (fp16).
// Last scanner CTA resets both counters (all waits already passed).
// =========================================================================
#define T1      256
#define NT      512
#define MAXIDX  256
#define NTILE_F (FEAT / 32)                 // 1280
#define NTILES  (NTILE_F * (HID / 64))      // 20480

__global__ __launch_bounds__(T1) void mega_kernel(
    const float* __restrict__ wf,    // [B, FEAT]
    const float* __restrict__ bfeat, // [B, FEAT]
    const float* __restrict__ stm,   // [B, 1]
    const float* __restrict__ ftw,   // [HID, FEAT]
    const float* __restrict__ ft_b,  // [HID]
    const float* __restrict__ l1_w)  // [64, 2048]
{
    __shared__ union {
        float tile[64][33];
        struct { int idxW[MAXIDX]; int idxB[MAXIDX]; int cw; int cb; } s;
    } sm;

    const int tid = threadIdx.x;

    if (blockIdx.x < NT) {
        for (int t = blockIdx.x; t < NTILES; t += NT) {
            const int f0 = (t % NTILE_F) * 32;
            const int h0 = (t / NTILE_F) * 64;
#pragma unroll
            for (int u = 0; u < 8; u++) {
                int idx = tid + u * T1;
                int hl = idx >> 5, fl = idx & 31;
                sm.tile[hl][fl] = __ldcs(ftw + (size_t)(h0 + hl) * FEAT + f0 + fl);
            }
            __syncthreads();
#pragma unroll
            for (int u = 0; u < 4; u++) {
                int idx = tid + u * T1;
                int fl = idx >> 5, hp = idx & 31;
                __half2 v = __floats2half2_rn(sm.tile[2 * hp][fl], sm.tile[2 * hp + 1][fl]);
                *reinterpret_cast<__half2*>(g_ftT + (size_t)(f0 + fl) * HID + h0 + 2 * hp) = v;
            }
            __syncthreads();
        }
        if (blockIdx.x < 128) {
            const int base = blockIdx.x * 1024 + tid * 4;
            float4 v = *reinterpret_cast<const float4*>(l1_w + base);
            __half2 lo = __floats2half2_rn(v.x, v.y);
            __half2 hi = __floats2half2_rn(v.z, v.w);
            *reinterpret_cast<__half2*>(g_l1w + base)     = lo;
            *reinterpret_cast<__half2*>(g_l1w + base + 2) = hi;
        }
        __threadfence();
        __syncthreads();
        if (tid == 0) atomicAdd(&g_done, 1);
        return;
    }

    // ---------------- scan ----------------
    const int b = blockIdx.x - NT;

    if (tid == 0) { sm.s.cw = 0; sm.s.cb = 0; }
    __syncthreads();
    {
        const float4* pw = (const float4*)(wf    + (size_t)b * FEAT);
        const float4* pb = (const float4*)(bfeat + (size_t)b * FEAT);
        for (int base = 0; base < FEAT / 4; base += 4 * T1) {
            float4 v[4], w[4];
#pragma unroll
            for (int u = 0; u < 4; u++) {
                v[u] = __ldcs(pw + base + tid + u * T1);
                w[u] = __ldcs(pb + base + tid + u * T1);
            }
#pragma unroll
            for (int u = 0; u < 4; u++) {
                int i = base + tid + u * T1;
                if (v[u].x != 0.f) { int q = atomicAdd(&sm.s.cw, 1); if (q < MAXIDX) sm.s.idxW[q] = 4*i;   }
                if (v[u].y != 0.f) { int q = atomicAdd(&sm.s.cw, 1); if (q < MAXIDX) sm.s.idxW[q] = 4*i+1; }
                if (v[u].z != 0.f) { int q = atomicAdd(&sm.s.cw, 1); if (q < MAXIDX) sm.s.idxW[q] = 4*i+2; }
                if (v[u].w != 0.f) { int q = atomicAdd(&sm.s.cw, 1); if (q < MAXIDX) sm.s.idxW[q] = 4*i+3; }
                if (w[u].x != 0.f) { int q = atomicAdd(&sm.s.cb, 1); if (q < MAXIDX) sm.s.idxB[q] = 4*i;   }
                if (w[u].y != 0.f) { int q = atomicAdd(&sm.s.cb, 1); if (q < MAXIDX) sm.s.idxB[q] = 4*i+1; }
                if (w[u].z != 0.f) { int q = atomicAdd(&sm.s.cb, 1); if (q < MAXIDX) sm.s.idxB[q] = 4*i+2; }
                if (w[u].w != 0.f) { int q = atomicAdd(&sm.s.cb, 1); if (q < MAXIDX) sm.s.idxB[q] = 4*i+3; }
            }
        }
    }
    __syncthreads();

    if (tid == 0) {
        while (atomicAdd(&g_done, 0) < NT) __nanosleep(128);
    }
    __syncthreads();
    __threadfence();

    // ---------------- gather ----------------
    const float4 bias = *reinterpret_cast<const float4*>(ft_b + 4 * tid);
    float4 accW = bias, accB = bias;
    const int nW = min(sm.s.cw, MAXIDX);
#pragma unroll 4
    for (int j = 0; j < nW; j++) {
        const uint2 raw = *reinterpret_cast<const uint2*>(
            g_ftT + (size_t)sm.s.idxW[j] * HID + 4 * tid);
        const float2 lo = __half22float2(*reinterpret_cast<const __half2*>(&raw.x));
        const float2 hi = __half22float2(*reinterpret_cast<const __half2*>(&raw.y));
        accW.x += lo.x; accW.y += lo.y; accW.z += hi.x; accW.w += hi.y;
    }
    const int nB = min(sm.s.cb, MAXIDX);
#pragma unroll 4
    for (int j = 0; j < nB; j++) {
        const uint2 raw = *reinterpret_cast<const uint2*>(
            g_ftT + (size_t)sm.s.idxB[j] * HID + 4 * tid);
        const float2 lo = __half22float2(*reinterpret_cast<const __half2*>(&raw.x));
        const float2 hi = __half22float2(*reinterpret_cast<const __half2*>(&raw.y));
        accB.x += lo.x; accB.y += lo.y; accB.z += hi.x; accB.w += hi.y;
    }

    // stm select + clip + store h1 (fp16)
    const float s = __ldg(stm + b);
    float cw[4] = {fminf(fmaxf(accW.x,0.f),1.f), fminf(fmaxf(accW.y,0.f),1.f),
                   fminf(fmaxf(accW.z,0.f),1.f), fminf(fmaxf(accW.w,0.f),1.f)};
    float cb[4] = {fminf(fmaxf(accB.x,0.f),1.f), fminf(fmaxf(accB.y,0.f),1.f),
                   fminf(fmaxf(accB.z,0.f),1.f), fminf(fmaxf(accB.w,0.f),1.f)};
    __half* o = g_h1 + (size_t)b * HID2;
    uint2 pf, ps;
    *reinterpret_cast<__half2*>(&pf.x) = __floats2half2_rn(
        s*cw[0]+(1.f-s)*cb[0], s*cw[1]+(1.f-s)*cb[1]);
    *reinterpret_cast<__half2*>(&pf.y) = __floats2half2_rn(
        s*cw[2]+(1.f-s)*cb[2], s*cw[3]+(1.f-s)*cb[3]);
    *reinterpret_cast<__half2*>(&ps.x) = __floats2half2_rn(
        s*cb[0]+(1.f-s)*cw[0], s*cb[1]+(1.f-s)*cw[1]);
    *reinterpret_cast<__half2*>(&ps.y) = __floats2half2_rn(
        s*cb[2]+(1.f-s)*cw[2], s*cb[3]+(1.f-s)*cw[3]);
    *reinterpret_cast<uint2*>(o + 4 * tid)       = pf;
    *reinterpret_cast<uint2*>(o + HID + 4 * tid) = ps;

    // ---- self-reset for graph replay ----
    __syncthreads();
    if (tid == 0) {
        int v = atomicAdd(&g_scan_done, 1);
        if (v == BATCH - 1) {
            g_done = 0;
            atomicExch(&g_scan_done, 0);
        }
    }
}

// =========================================================================
// Tensor-core MLP with smem-staged double-buffered fragments.
// 128 CTAs x 256 threads (8 warps). Warp w: 16-row tile mr=w&1, 16-out nc=w>>1.
// Chunk = 64 k: h-tile 32x64 fp16 (1 uint4/thread), w-tile 64x64 fp16
// (2 uint4/thread) -> smem (pad +8 halves, row stride 144B = 9x16B).
// 4 wmma k-steps per chunk from smem; next chunk's loads in flight.
// =========================================================================
#define T2  256
#define KC  64
#define NKC (HID2 / KC)     // 32
#define HP  (KC + 8)        // 72 halves = 144 B

__global__ __launch_bounds__(T2) void mlp_kernel(
    const float* __restrict__ l1_b,
    const float* __restrict__ l2_w, const float* __restrict__ l2_b,
    const float* __restrict__ l3_w, const float* __restrict__ l3_b,
    float* __restrict__ out, int out_size)
{
    __shared__ __align__(16) __half hA[2][GRP][HP];    // 9.2 KB
    __shared__ __align__(16) __half wB[2][NL1][HP];    // 18.4 KB
    __shared__ float h2s[GRP][72];                     // 9.2 KB (wmma store)
    __shared__ float h3s[GRP][NL2 + 1];
    __shared__ float l2s[NL2][NL1 + 1];

    const int tid  = threadIdx.x;
    const int wid  = tid >> 5;
    const int row0 = blockIdx.x * GRP;
    const int mr   = wid & 1;
    const int nc   = wid >> 1;

    for (int i = tid; i < NL2 * NL1; i += T2) l2s[i >> 6][i & 63] = l2_w[i];

    // staging indices: h-tile, 256 segs of 8 halves (row r = tid>>3, seg tid&7)
    const int hr = tid >> 3, hs = (tid & 7) * 8;
    // w-tile: 512 segs -> 2 per thread
    const int wr0 = tid >> 2,           ws0 = (tid & 3) * 16;        // 2 segs side by side

    uint4 hreg, wreg[2];
    {
        hreg = *reinterpret_cast<const uint4*>(g_h1 + (size_t)(row0 + hr) * HID2 + hs);
        wreg[0] = *reinterpret_cast<const uint4*>(g_l1w + (size_t)wr0 * HID2 + ws0);
        wreg[1] = *reinterpret_cast<const uint4*>(g_l1w + (size_t)wr0 * HID2 + ws0 + 8);
        *reinterpret_cast<uint4*>(&hA[0][hr][hs]) = hreg;
        *reinterpret_cast<uint4*>(&wB[0][wr0][ws0])     = wreg[0];
        *reinterpret_cast<uint4*>(&wB[0][wr0][ws0 + 8]) = wreg[1];
    }
    __syncthreads();

    wmma::fragment<wmma::accumulator, 16, 16, 16, float> c;
    wmma::fill_fragment(c, 0.f);

    for (int ch = 0; ch < NKC; ch++) {
        const int buf = ch & 1;
        if (ch + 1 < NKC) {
            const int kc = (ch + 1) * KC;
            hreg = *reinterpret_cast<const uint4*>(
                g_h1 + (size_t)(row0 + hr) * HID2 + kc + hs);
            wreg[0] = *reinterpret_cast<const uint4*>(
                g_l1w + (size_t)wr0 * HID2 + kc + ws0);
            wreg[1] = *reinterpret_cast<const uint4*>(
                g_l1w + (size_t)wr0 * HID2 + kc + ws0 + 8);
        }
#pragma unroll
        for (int kk = 0; kk < KC / 16; kk++) {
            wmma::fragment<wmma::matrix_a, 16, 16, 16, __half, wmma::row_major> a;
            wmma::fragment<wmma::matrix_b, 16, 16, 16, __half, wmma::col_major> bf;
            wmma::load_matrix_sync(a,  &hA[buf][mr * 16][kk * 16], HP);
            wmma::load_matrix_sync(bf, &wB[buf][nc * 16][kk * 16], HP);
            wmma::mma_sync(c, a, bf, c);
        }
        if (ch + 1 < NKC) {
            const int nb = (ch + 1) & 1;
            *reinterpret_cast<uint4*>(&hA[nb][hr][hs]) = hreg;
            *reinterpret_cast<uint4*>(&wB[nb][wr0][ws0])     = wreg[0];
            *reinterpret_cast<uint4*>(&wB[nb][wr0][ws0 + 8]) = wreg[1];
        }
        __syncthreads();
    }

    wmma::store_matrix_sync(&h2s[mr * 16][nc * 16], c, 72, wmma::mem_row_major);
    __syncthreads();

    // ---- bias + clip (in place) ----
    for (int p = tid; p < GRP * NL1; p += T2) {
        int r = p >> 6, o = p & 63;
        float v = h2s[r][o] + __ldg(l1_b + o);
        h2s[r][o] = fminf(fmaxf(v, 0.f), 1.f);
    }
    __syncthreads();

    // ---- l2 ----
    for (int p = tid; p < GRP * NL2; p += T2) {
        int r = p >> 5, oo = p & 31;
        float s = __ldg(l2_b + oo);
#pragma unroll
        for (int k = 0; k < NL1; k++) s = fmaf(h2s[r][k], l2s[oo][k], s);
        h3s[r][oo] = fminf(fmaxf(s, 0.f), 1.f);
    }
    __syncthreads();

    // ---- l3 + sigmoid ----
    if (tid < GRP) {
        float s = __ldg(l3_b);
#pragma unroll
        for (int k = 0; k < NL2; k++) s = fmaf(h3s[tid][k], __ldg(l3_w + k), s);
        float sig = 1.f / (1.f + expf(-s));
        int r = row0 + tid;
        if (out_size >= 2 * BATCH) {
            out[r]         = sig;
            out[BATCH + r] = s;
        } else {
            out[r] = sig;
        }
    }
}

// =========================================================================
extern "C" void kernel_launch(void* const* d_in, const int* in_sizes, int n_in,
                              void* d_out, int out_size)
{
    const float* wf    = (const float*)d_in[0];
    const float* bfeat = (const float*)d_in[1];
    const float* stm   = (const float*)d_in[2];
    const float* ft_w  = (const float*)d_in[3];
    const float* ft_b  = (const float*)d_in[4];
    const float* l1_w  = (const float*)d_in[5];
    const float* l1_b  = (const float*)d_in[6];
    const float* l2_w  = (const float*)d_in[7];
    const float* l2_b  = (const float*)d_in[8];
    const float* l3_w  = (const float*)d_in[9];
    const float* l3_b  = (const float*)d_in[10];
    float* out = (float*)d_out;

    mega_kernel<<<NT + BATCH, T1>>>(wf, bfeat, stm, ft_w, ft_b, l1_w);
    mlp_kernel<<<NGRP, T2>>>(l1_b, l2_w, l2_b, l3_w, l3_b, out, out_size);
}

// round 17
// speedup vs baseline: 1.1766x; 1.0323x over previous
#include <cuda_runtime.h>
#include <cuda_fp16.h>
#include <mma.h>
#include <math.h>

using namespace nvcuda;

#define BATCH 4096
#define FEAT  40960
#define HID   1024
#define HID2  2048
#define NL1   64
#define NL2   32
#define GRP   32
#define NGRP  (BATCH / GRP)     // 128

// ---------------- static device scratch (no allocs allowed) ----------------
__device__ __half g_ftT[(size_t)FEAT * HID];    // 83.9 MB
__device__ __half g_h1[(size_t)BATCH * HID2];   // 16.8 MB
__device__ __half g_l1w[(size_t)NL1 * HID2];    // 256 KB: l1_w fp16
__device__ int    g_done;        // transpose completion (self-resetting)
__device__ int    g_scan_done;   // scanner completion (self-resetting)

// =========================================================================
// Mega-kernel (R15/R16 verbatim, ~281us):
//   CTAs [0, NT)        : transpose ft_w -> g_ftT (fp16); CTAs [0,128) also
//                         convert l1_w -> fp16; signal g_done.
//   CTAs [NT, NT+BATCH) : scan -> wait -> gather -> h1 (fp16).
// Last scanner CTA resets both counters (all waits already passed).
// =========================================================================
#define T1      256
#define NT      512
#define MAXIDX  256
#define NTILE_F (FEAT / 32)                 // 1280
#define NTILES  (NTILE_F * (HID / 64))      // 20480

__global__ __launch_bounds__(T1) void mega_kernel(
    const float* __restrict__ wf,    // [B, FEAT]
    const float* __restrict__ bfeat, // [B, FEAT]
    const float* __restrict__ stm,   // [B, 1]
    const float* __restrict__ ftw,   // [HID, FEAT]
    const float* __restrict__ ft_b,  // [HID]
    const float* __restrict__ l1_w)  // [64, 2048]
{
    __shared__ union {
        float tile[64][33];
        struct { int idxW[MAXIDX]; int idxB[MAXIDX]; int cw; int cb; } s;
    } sm;

    const int tid = threadIdx.x;

    if (blockIdx.x < NT) {
        for (int t = blockIdx.x; t < NTILES; t += NT) {
            const int f0 = (t % NTILE_F) * 32;
            const int h0 = (t / NTILE_F) * 64;
#pragma unroll
            for (int u = 0; u < 8; u++) {
                int idx = tid + u * T1;
                int hl = idx >> 5, fl = idx & 31;
                sm.tile[hl][fl] = __ldcs(ftw + (size_t)(h0 + hl) * FEAT + f0 + fl);
            }
            __syncthreads();
#pragma unroll
            for (int u = 0; u < 4; u++) {
                int idx = tid + u * T1;
                int fl = idx >> 5, hp = idx & 31;
                __half2 v = __floats2half2_rn(sm.tile[2 * hp][fl], sm.tile[2 * hp + 1][fl]);
                *reinterpret_cast<__half2*>(g_ftT + (size_t)(f0 + fl) * HID + h0 + 2 * hp) = v;
            }
            __syncthreads();
        }
        if (blockIdx.x < 128) {
            const int base = blockIdx.x * 1024 + tid * 4;
            float4 v = *reinterpret_cast<const float4*>(l1_w + base);
            __half2 lo = __floats2half2_rn(v.x, v.y);
            __half2 hi = __floats2half2_rn(v.z, v.w);
            *reinterpret_cast<__half2*>(g_l1w + base)     = lo;
            *reinterpret_cast<__half2*>(g_l1w + base + 2) = hi;
        }
        __threadfence();
        __syncthreads();
        if (tid == 0) atomicAdd(&g_done, 1);
        return;
    }

    // ---------------- scan ----------------
    const int b = blockIdx.x - NT;

    if (tid == 0) { sm.s.cw = 0; sm.s.cb = 0; }
    __syncthreads();
    {
        const float4* pw = (const float4*)(wf    + (size_t)b * FEAT);
        const float4* pb = (const float4*)(bfeat + (size_t)b * FEAT);
        for (int base = 0; base < FEAT / 4; base += 4 * T1) {
            float4 v[4], w[4];
#pragma unroll
            for (int u = 0; u < 4; u++) {
                v[u] = __ldcs(pw + base + tid + u * T1);
                w[u] = __ldcs(pb + base + tid + u * T1);
            }
#pragma unroll
            for (int u = 0; u < 4; u++) {
                int i = base + tid + u * T1;
                if (v[u].x != 0.f) { int q = atomicAdd(&sm.s.cw, 1); if (q < MAXIDX) sm.s.idxW[q] = 4*i;   }
                if (v[u].y != 0.f) { int q = atomicAdd(&sm.s.cw, 1); if (q < MAXIDX) sm.s.idxW[q] = 4*i+1; }
                if (v[u].z != 0.f) { int q = atomicAdd(&sm.s.cw, 1); if (q < MAXIDX) sm.s.idxW[q] = 4*i+2; }
                if (v[u].w != 0.f) { int q = atomicAdd(&sm.s.cw, 1); if (q < MAXIDX) sm.s.idxW[q] = 4*i+3; }
                if (w[u].x != 0.f) { int q = atomicAdd(&sm.s.cb, 1); if (q < MAXIDX) sm.s.idxB[q] = 4*i;   }
                if (w[u].y != 0.f) { int q = atomicAdd(&sm.s.cb, 1); if (q < MAXIDX) sm.s.idxB[q] = 4*i+1; }
                if (w[u].z != 0.f) { int q = atomicAdd(&sm.s.cb, 1); if (q < MAXIDX) sm.s.idxB[q] = 4*i+2; }
                if (w[u].w != 0.f) { int q = atomicAdd(&sm.s.cb, 1); if (q < MAXIDX) sm.s.idxB[q] = 4*i+3; }
            }
        }
    }
    __syncthreads();

    if (tid == 0) {
        while (atomicAdd(&g_done, 0) < NT) __nanosleep(128);
    }
    __syncthreads();
    __threadfence();

    // ---------------- gather ----------------
    const float4 bias = *reinterpret_cast<const float4*>(ft_b + 4 * tid);
    float4 accW = bias, accB = bias;
    const int nW = min(sm.s.cw, MAXIDX);
#pragma unroll 4
    for (int j = 0; j < nW; j++) {
        const uint2 raw = *reinterpret_cast<const uint2*>(
            g_ftT + (size_t)sm.s.idxW[j] * HID + 4 * tid);
        const float2 lo = __half22float2(*reinterpret_cast<const __half2*>(&raw.x));
        const float2 hi = __half22float2(*reinterpret_cast<const __half2*>(&raw.y));
        accW.x += lo.x; accW.y += lo.y; accW.z += hi.x; accW.w += hi.y;
    }
    const int nB = min(sm.s.cb, MAXIDX);
#pragma unroll 4
    for (int j = 0; j < nB; j++) {
        const uint2 raw = *reinterpret_cast<const uint2*>(
            g_ftT + (size_t)sm.s.idxB[j] * HID + 4 * tid);
        const float2 lo = __half22float2(*reinterpret_cast<const __half2*>(&raw.x));
        const float2 hi = __half22float2(*reinterpret_cast<const __half2*>(&raw.y));
        accB.x += lo.x; accB.y += lo.y; accB.z += hi.x; accB.w += hi.y;
    }

    // stm select + clip + store h1 (fp16)
    const float s = __ldg(stm + b);
    float cw[4] = {fminf(fmaxf(accW.x,0.f),1.f), fminf(fmaxf(accW.y,0.f),1.f),
                   fminf(fmaxf(accW.z,0.f),1.f), fminf(fmaxf(accW.w,0.f),1.f)};
    float cb[4] = {fminf(fmaxf(accB.x,0.f),1.f), fminf(fmaxf(accB.y,0.f),1.f),
                   fminf(fmaxf(accB.z,0.f),1.f), fminf(fmaxf(accB.w,0.f),1.f)};
    __half* o = g_h1 + (size_t)b * HID2;
    uint2 pf, ps;
    *reinterpret_cast<__half2*>(&pf.x) = __floats2half2_rn(
        s*cw[0]+(1.f-s)*cb[0], s*cw[1]+(1.f-s)*cb[1]);
    *reinterpret_cast<__half2*>(&pf.y) = __floats2half2_rn(
        s*cw[2]+(1.f-s)*cb[2], s*cw[3]+(1.f-s)*cb[3]);
    *reinterpret_cast<__half2*>(&ps.x) = __floats2half2_rn(
        s*cb[0]+(1.f-s)*cw[0], s*cb[1]+(1.f-s)*cw[1]);
    *reinterpret_cast<__half2*>(&ps.y) = __floats2half2_rn(
        s*cb[2]+(1.f-s)*cw[2], s*cb[3]+(1.f-s)*cw[3]);
    *reinterpret_cast<uint2*>(o + 4 * tid)       = pf;
    *reinterpret_cast<uint2*>(o + HID + 4 * tid) = ps;

    // ---- self-reset for graph replay ----
    __syncthreads();
    if (tid == 0) {
        int v = atomicAdd(&g_scan_done, 1);
        if (v == BATCH - 1) {
            g_done = 0;
            atomicExch(&g_scan_done, 0);
        }
    }
}

// =========================================================================
// Tensor-core MLP, KC=128 chunks (16 stages), double-buffered smem staging.
// 128 CTAs x 256 threads (8 warps). Warp w: mr = w&1 (16-row), nc = w>>1.
// Epilogue arrays union with staging buffers (used only after the k-loop).
// =========================================================================
#define T2  256
#define KC  128
#define NKC (HID2 / KC)     // 16
#define HP  (KC + 8)        // 136 halves = 272 B row stride

__global__ __launch_bounds__(T2) void mlp_kernel(
    const float* __restrict__ l1_b,
    const float* __restrict__ l2_w, const float* __restrict__ l2_b,
    const float* __restrict__ l3_w, const float* __restrict__ l3_b,
    float* __restrict__ out, int out_size)
{
    __shared__ union {
        struct {
            __align__(16) __half hA[2][GRP][HP];   // 17.4 KB
            __align__(16) __half wB[2][NL1][HP];   // 34.8 KB
        } st;                                      // 52.2 KB
        struct {
            float h2s[GRP][72];                    // 9.2 KB (wmma store, ldm 72)
            float h3s[GRP][NL2 + 1];
            float l2s[NL2][NL1 + 1];
        } ep;
    } sm;

    const int tid  = threadIdx.x;
    const int wid  = tid >> 5;
    const int row0 = blockIdx.x * GRP;
    const int mr   = wid & 1;
    const int nc   = wid >> 1;

    // staging maps (uint4 = 8 halves):
    // h-tile 32x128 = 512 segs -> 2/thread ; w-tile 64x128 = 1024 segs -> 4/thread
    const int hr = tid >> 4, hs = (tid & 15) * 8;          // rows 0..15? no: idx-based below
    uint4 hreg[2], wreg[4];
    {
#pragma unroll
        for (int u = 0; u < 2; u++) {
            int idx = tid + u * T2; int r = idx >> 4, ss = (idx & 15) * 8;
            hreg[u] = *reinterpret_cast<const uint4*>(
                g_h1 + (size_t)(row0 + r) * HID2 + ss);
        }
#pragma unroll
        for (int u = 0; u < 4; u++) {
            int idx = tid + u * T2; int r = idx >> 4, ss = (idx & 15) * 8;
            wreg[u] = *reinterpret_cast<const uint4*>(
                g_l1w + (size_t)r * HID2 + ss);
        }
#pragma unroll
        for (int u = 0; u < 2; u++) {
            int idx = tid + u * T2; int r = idx >> 4, ss = (idx & 15) * 8;
            *reinterpret_cast<uint4*>(&sm.st.hA[0][r][ss]) = hreg[u];
        }
#pragma unroll
        for (int u = 0; u < 4; u++) {
            int idx = tid + u * T2; int r = idx >> 4, ss = (idx & 15) * 8;
            *reinterpret_cast<uint4*>(&sm.st.wB[0][r][ss]) = wreg[u];
        }
    }
    __syncthreads();

    wmma::fragment<wmma::accumulator, 16, 16, 16, float> c;
    wmma::fill_fragment(c, 0.f);

    for (int ch = 0; ch < NKC; ch++) {
        const int buf = ch & 1;
        if (ch + 1 < NKC) {
            const int kc = (ch + 1) * KC;
#pragma unroll
            for (int u = 0; u < 2; u++) {
                int idx = tid + u * T2; int r = idx >> 4, ss = (idx & 15) * 8;
                hreg[u] = *reinterpret_cast<const uint4*>(
                    g_h1 + (size_t)(row0 + r) * HID2 + kc + ss);
            }
#pragma unroll
            for (int u = 0; u < 4; u++) {
                int idx = tid + u * T2; int r = idx >> 4, ss = (idx & 15) * 8;
                wreg[u] = *reinterpret_cast<const uint4*>(
                    g_l1w + (size_t)r * HID2 + kc + ss);
            }
        }
#pragma unroll
        for (int kk = 0; kk < KC / 16; kk++) {
            wmma::fragment<wmma::matrix_a, 16, 16, 16, __half, wmma::row_major> a;
            wmma::fragment<wmma::matrix_b, 16, 16, 16, __half, wmma::col_major> bf;
            wmma::load_matrix_sync(a,  &sm.st.hA[buf][mr * 16][kk * 16], HP);
            wmma::load_matrix_sync(bf, &sm.st.wB[buf][nc * 16][kk * 16], HP);
            wmma::mma_sync(c, a, bf, c);
        }
        if (ch + 1 < NKC) {
            const int nb = (ch + 1) & 1;
#pragma unroll
            for (int u = 0; u < 2; u++) {
                int idx = tid + u * T2; int r = idx >> 4, ss = (idx & 15) * 8;
                *reinterpret_cast<uint4*>(&sm.st.hA[nb][r][ss]) = hreg[u];
            }
#pragma unroll
            for (int u = 0; u < 4; u++) {
                int idx = tid + u * T2; int r = idx >> 4, ss = (idx & 15) * 8;
                *reinterpret_cast<uint4*>(&sm.st.wB[nb][r][ss]) = wreg[u];
            }
        }
        __syncthreads();
    }

    // ---- epilogue (staging buffers dead; union reused) ----
    wmma::store_matrix_sync(&sm.ep.h2s[mr * 16][nc * 16], c, 72, wmma::mem_row_major);
    __syncthreads();

    for (int i = tid; i < NL2 * NL1; i += T2) sm.ep.l2s[i >> 6][i & 63] = l2_w[i];

    // bias + clip (in place)
    for (int p = tid; p < GRP * NL1; p += T2) {
        int r = p >> 6, o = p & 63;
        float v = sm.ep.h2s[r][o] + __ldg(l1_b + o);
        sm.ep.h2s[r][o] = fminf(fmaxf(v, 0.f), 1.f);
    }
    __syncthreads();

    // l2
    for (int p = tid; p < GRP * NL2; p += T2) {
        int r = p >> 5, oo = p & 31;
        float s = __ldg(l2_b + oo);
#pragma unroll
        for (int k = 0; k < NL1; k++) s = fmaf(sm.ep.h2s[r][k], sm.ep.l2s[oo][k], s);
        sm.ep.h3s[r][oo] = fminf(fmaxf(s, 0.f), 1.f);
    }
    __syncthreads();

    // l3 + sigmoid
    if (tid < GRP) {
        float s = __ldg(l3_b);
#pragma unroll
        for (int k = 0; k < NL2; k++) s = fmaf(sm.ep.h3s[tid][k], __ldg(l3_w + k), s);
        float sig = 1.f / (1.f + expf(-s));
        int r = row0 + tid;
        if (out_size >= 2 * BATCH) {
            out[r]         = sig;
            out[BATCH + r] = s;
        } else {
            out[r] = sig;
        }
    }
}

// =========================================================================
extern "C" void kernel_launch(void* const* d_in, const int* in_sizes, int n_in,
                              void* d_out, int out_size)
{
    const float* wf    = (const float*)d_in[0];
    const float* bfeat = (const float*)d_in[1];
    const float* stm   = (const float*)d_in[2];
    const float* ft_w  = (const float*)d_in[3];
    const float* ft_b  = (const float*)d_in[4];
    const float* l1_w  = (const float*)d_in[5];
    const float* l1_b  = (const float*)d_in[6];
    const float* l2_w  = (const float*)d_in[7];
    const float* l2_b  = (const float*)d_in[8];
    const float* l3_w  = (const float*)d_in[9];
    const float* l3_b  = (const float*)d_in[10];
    float* out = (float*)d_out;

    mega_kernel<<<NT + BATCH, T1>>>(wf, bfeat, stm, ft_w, ft_b, l1_w);
    mlp_kernel<<<NGRP, T2>>>(l1_b, l2_w, l2_b, l3_w, l3_b, out, out_size);
}